// round 12
// baseline (speedup 1.0000x reference)
#include <cuda_runtime.h>
#include <cstdint>

#define NBATCH 256
#define NN     64
#define DT     4096
#define THREADS 256

#define XSTR 136                       // floats; 136 % 32 == 8 -> conflict-free B LDS
#define WSTR 68
#define SMF_W  0                       // 64*68      = 4352 floats
#define SMF_X0 (SMF_W + NN * WSTR)     // 64*136     = 8704 floats
#define SMF_X1 (SMF_X0 + NN * XSTR)
#define SMF_E  (SMF_X1 + NN * XSTR)
#define SMF_CF (SMF_E + NN)
#define SMEM_FLOATS (SMF_CF + 8)
#define SMEM_BYTES  (SMEM_FLOATS * 4)  // ~87.6 KB -> 2 CTAs/SM

__device__ __forceinline__ uint32_t f2tf32(float f) {
    uint32_t r;
    asm("cvt.rna.tf32.f32 %0, %1;" : "=r"(r) : "f"(f));
    return r;
}
__device__ __forceinline__ void mma_tf32(float& c0, float& c1, float& c2, float& c3,
                                         uint32_t a0, uint32_t a1, uint32_t a2, uint32_t a3,
                                         uint32_t b0, uint32_t b1) {
    asm volatile(
        "mma.sync.aligned.m16n8k8.row.col.f32.tf32.tf32.f32 "
        "{%0,%1,%2,%3}, {%4,%5,%6,%7}, {%8,%9}, {%0,%1,%2,%3};"
        : "+f"(c0), "+f"(c1), "+f"(c2), "+f"(c3)
        : "r"(a0), "r"(a1), "r"(a2), "r"(a3), "r"(b0), "r"(b1));
}
__device__ __forceinline__ void cp_async16(void* smem_dst, const void* gsrc) {
    unsigned sa = (unsigned)__cvta_generic_to_shared(smem_dst);
    asm volatile("cp.async.cg.shared.global [%0], [%1], 16;" :: "r"(sa), "l"(gsrc));
}
__device__ __forceinline__ void stg_cs_f2(float* p, float a, float b) {
    asm volatile("st.global.cs.v2.f32 [%0], {%1, %2};" :: "l"(p), "f"(a), "f"(b));
}

// ============================================================================
// Fused: variance -> coefs -> masked softmax -> tf32 mma GEMM + fp32 residual
// Grid 256 (1 CTA per batch), 256 threads, 2 CTAs/SM.
// Chunks stage fp32 via cp.async, are converted IN PLACE to tf32 once
// (deduped cvt), mainloop does pure LDS+mma; residual re-read from gmem (L2).
// ============================================================================
__global__ void __launch_bounds__(THREADS, 2)
dga_fused(const float* __restrict__ x,  const float* __restrict__ wq,
          const float* __restrict__ bq, const float* __restrict__ wk,
          const float* __restrict__ bk, float* __restrict__ out,
          float* __restrict__ attn)
{
    extern __shared__ float smf[];
    float* w_sm = smf + SMF_W;
    float* e_sm = smf + SMF_E;
    float* coef = smf + SMF_CF;
    float* xbuf0 = smf + SMF_X0;
    float* xbuf1 = smf + SMF_X1;

    const int b    = blockIdx.x;
    const int tid  = threadIdx.x;
    const int warp = tid >> 5;
    const int lane = tid & 31;
    const float* xb = x + (size_t)b * NN * DT;
    float*       ob = out + (size_t)b * NN * DT;

    // ---- Prologue: stage chunk 0 now; it fills under the variance scan ----
    #pragma unroll
    for (int s = 0; s < 8; ++s) {
        int u = tid + 256 * s;
        int j = u >> 5, q = u & 31;
        cp_async16(&xbuf0[j * XSTR + q * 4], xb + (size_t)j * DT + q * 4);
    }
    asm volatile("cp.async.commit_group;");

    // ---- Phase 1: row variances (ddof=1). 8 warps, 8 rows each. ----
    for (int r = warp; r < NN; r += 8) {
        const float4* row = (const float4*)(xb + (size_t)r * DT);
        float s = 0.f, ss = 0.f;
        #pragma unroll
        for (int k = 0; k < 32; ++k) {
            float4 v = row[lane + 32 * k];
            s  += (v.x + v.y) + (v.z + v.w);
            ss += v.x * v.x + v.y * v.y + v.z * v.z + v.w * v.w;
        }
        #pragma unroll
        for (int m = 16; m; m >>= 1) {
            s  += __shfl_xor_sync(0xffffffffu, s,  m);
            ss += __shfl_xor_sync(0xffffffffu, ss, m);
        }
        if (lane == 0) {
            float mean = s * (1.0f / DT);
            e_sm[r] = (ss - s * mean) * (1.0f / (DT - 1));
        }
    }
    if (tid == 0) {
        float A = 0.f, B = 0.f, C = 0.f, Dc = 0.f;
        #pragma unroll
        for (int h = 0; h < 16; ++h) {
            float q = wq[h], qb = bq[h], k = wk[h], kb = bk[h];
            A += q * k; B += q * kb; C += qb * k; Dc += qb * kb;
        }
        coef[0] = A; coef[1] = B; coef[2] = C; coef[3] = Dc;
    }
    __syncthreads();

    // ---- Phase 2: masked softmax; 4 threads/row. diag weight == exactly 0 ----
    {
        const int i  = tid >> 2;
        const int jg = tid & 3;
        const float ei = e_sm[i];
        const float m1 = 0.25f * (coef[0] * ei + coef[2]);   // SCALE = 0.25
        const float m0 = 0.25f * (coef[1] * ei + coef[3]);
        float sv[16];
        float mx = -3.4e38f;
        #pragma unroll
        for (int t = 0; t < 16; ++t) {
            int j = jg * 16 + t;
            float s = fmaf(m1, e_sm[j], m0);
            if (j == i) s = -1000000000.0f;
            sv[t] = s;
            mx = fmaxf(mx, s);
        }
        #pragma unroll
        for (int m = 1; m < 4; m <<= 1)
            mx = fmaxf(mx, __shfl_xor_sync(0xffffffffu, mx, m));
        float sum = 0.f;
        #pragma unroll
        for (int t = 0; t < 16; ++t) { sv[t] = __expf(sv[t] - mx); sum += sv[t]; }
        #pragma unroll
        for (int m = 1; m < 4; m <<= 1)
            sum += __shfl_xor_sync(0xffffffffu, sum, m);
        float inv = 1.0f / sum;

        float* arow = attn + (((size_t)b * NN) + i) * NN;
        #pragma unroll
        for (int t = 0; t < 16; ++t) {
            float w = sv[t] * inv;
            arow[jg * 16 + t] = w;
            w_sm[i * WSTR + jg * 16 + t] = w;
        }
    }
    __syncthreads();

    // ---- Phase 3: preload A-fragments (W as tf32) into registers ----
    const int mw  = (warp & 3) * 16;       // warp's 16 output rows
    const int nco = (warp >> 2) * 64;      // warp's 64-col slice within chunk
    const int g   = lane >> 2;
    const int tg  = lane & 3;

    uint32_t A[8][4];
    #pragma unroll
    for (int ks = 0; ks < 8; ++ks) {
        A[ks][0] = f2tf32(w_sm[(mw + g)     * WSTR + ks * 8 + tg]);
        A[ks][1] = f2tf32(w_sm[(mw + g + 8) * WSTR + ks * 8 + tg]);
        A[ks][2] = f2tf32(w_sm[(mw + g)     * WSTR + ks * 8 + tg + 4]);
        A[ks][3] = f2tf32(w_sm[(mw + g + 8) * WSTR + ks * 8 + tg + 4]);
    }

    // ---- Phase 4: 32 chunks of 128 t, double-buffered; in-place cvt ----
    #pragma unroll 1
    for (int c = 0; c < 32; ++c) {
        const int t0 = c * 128;
        float* xc = (c & 1) ? xbuf1 : xbuf0;

        if (c + 1 < 32) {
            float* xn = (c & 1) ? xbuf0 : xbuf1;
            const float* src = xb + (t0 + 128);
            #pragma unroll
            for (int s = 0; s < 8; ++s) {
                int u = tid + 256 * s;
                int j = u >> 5, q = u & 31;
                cp_async16(&xn[j * XSTR + q * 4], src + (size_t)j * DT + q * 4);
            }
            asm volatile("cp.async.commit_group;");
            asm volatile("cp.async.wait_group 1;");
        } else {
            asm volatile("cp.async.wait_group 0;");
        }
        __syncthreads();

        // in-place tf32 conversion: each thread converts what it staged
        #pragma unroll
        for (int s = 0; s < 8; ++s) {
            int u = tid + 256 * s;
            int j = u >> 5, q = u & 31;
            float4* p = (float4*)&xc[j * XSTR + q * 4];
            float4 v = *p;
            uint4 w;
            w.x = f2tf32(v.x); w.y = f2tf32(v.y);
            w.z = f2tf32(v.z); w.w = f2tf32(v.w);
            *(uint4*)p = w;
        }
        __syncthreads();

        // mainloop: pure LDS.32 (tf32 bits) + mma
        const uint32_t* xt = (const uint32_t*)xc;
        float C[8][4];
        #pragma unroll
        for (int t = 0; t < 8; ++t)
            C[t][0] = C[t][1] = C[t][2] = C[t][3] = 0.f;

        #pragma unroll
        for (int ks = 0; ks < 8; ++ks) {
            const uint32_t* b0r = &xt[(ks * 8 + tg)     * XSTR + nco + g];
            const uint32_t* b1r = &xt[(ks * 8 + tg + 4) * XSTR + nco + g];
            #pragma unroll
            for (int t = 0; t < 8; ++t) {
                uint32_t b0 = b0r[t * 8];         // single-phase LDS.32
                uint32_t b1 = b1r[t * 8];
                mma_tf32(C[t][0], C[t][1], C[t][2], C[t][3],
                         A[ks][0], A[ks][1], A[ks][2], A[ks][3], b0, b1);
            }
        }

        // epilogue: exact fp32 residual from gmem (L2-hot), streaming stores
        #pragma unroll
        for (int t = 0; t < 8; ++t) {
            int lcol = nco + t * 8 + 2 * tg;
            const float2 r0 = *(const float2*)(xb + (size_t)(mw + g)     * DT + t0 + lcol);
            const float2 r1 = *(const float2*)(xb + (size_t)(mw + g + 8) * DT + t0 + lcol);
            stg_cs_f2(ob + (size_t)(mw + g)     * DT + t0 + lcol,
                      C[t][0] + r0.x, C[t][1] + r0.y);
            stg_cs_f2(ob + (size_t)(mw + g + 8) * DT + t0 + lcol,
                      C[t][2] + r1.x, C[t][3] + r1.y);
        }
        __syncthreads();   // compute(c) done before restaging this buffer
    }
}

extern "C" void kernel_launch(void* const* d_in, const int* in_sizes, int n_in,
                              void* d_out, int out_size) {
    const float* x  = (const float*)d_in[0];
    const float* wq = (const float*)d_in[1];
    const float* bq = (const float*)d_in[2];
    const float* wk = (const float*)d_in[3];
    const float* bk = (const float*)d_in[4];
    float* out  = (float*)d_out;
    float* attn = out + (size_t)NBATCH * NN * DT;   // out tensor first, then attn

    cudaFuncSetAttribute(dga_fused, cudaFuncAttributeMaxDynamicSharedMemorySize,
                         SMEM_BYTES);
    dga_fused<<<NBATCH, THREADS, SMEM_BYTES>>>(x, wq, bq, wk, bk, out, attn);
}

// round 13
// speedup vs baseline: 1.2787x; 1.2787x over previous
#include <cuda_runtime.h>
#include <cstdint>

#define NBATCH 256
#define NN     64
#define DT     4096
#define THREADS 256

__device__ float e_scratch[NBATCH * NN];

#define XSTR 136                       // floats; 136 % 32 == 8 -> conflict-free B LDS
#define WSTR 68
#define SMF_W  0                       // 64*68  = 4352 floats
#define SMF_X0 (SMF_W + NN * WSTR)     // 64*136 = 8704 floats
#define SMF_X1 (SMF_X0 + NN * XSTR)
#define SMF_E  (SMF_X1 + NN * XSTR)
#define SMF_CF (SMF_E + NN)
#define SMEM_FLOATS (SMF_CF + 8)
#define SMEM_BYTES  (SMEM_FLOATS * 4)  // ~87.4 KB -> 2 CTAs/SM

__device__ __forceinline__ uint32_t f2tf32(float f) {
    uint32_t r;
    asm("cvt.rna.tf32.f32 %0, %1;" : "=r"(r) : "f"(f));
    return r;
}
__device__ __forceinline__ void mma_tf32(float& c0, float& c1, float& c2, float& c3,
                                         uint32_t a0, uint32_t a1, uint32_t a2, uint32_t a3,
                                         uint32_t b0, uint32_t b1) {
    asm volatile(
        "mma.sync.aligned.m16n8k8.row.col.f32.tf32.tf32.f32 "
        "{%0,%1,%2,%3}, {%4,%5,%6,%7}, {%8,%9}, {%0,%1,%2,%3};"
        : "+f"(c0), "+f"(c1), "+f"(c2), "+f"(c3)
        : "r"(a0), "r"(a1), "r"(a2), "r"(a3), "r"(b0), "r"(b1));
}
__device__ __forceinline__ void cp_async16(void* smem_dst, const void* gsrc) {
    unsigned sa = (unsigned)__cvta_generic_to_shared(smem_dst);
    asm volatile("cp.async.cg.shared.global [%0], [%1], 16;" :: "r"(sa), "l"(gsrc));
}

// ============================================================================
// K1a: row variances (ddof=1). 1024 blocks, 2-row interleave (80.9% DRAM).
// ============================================================================
__global__ void __launch_bounds__(THREADS, 4)
dga_var(const float* __restrict__ x)
{
    const int b    = blockIdx.x >> 2;
    const int g    = blockIdx.x & 3;
    const int warp = threadIdx.x >> 5;
    const int lane = threadIdx.x & 31;
    const float* xb = x + (size_t)b * NN * DT;

    const int r0 = g * 16 + warp * 2;
    const float4* rowA = (const float4*)(xb + (size_t)r0 * DT);
    const float4* rowB = (const float4*)(xb + (size_t)(r0 + 1) * DT);
    float sA = 0.f, ssA = 0.f, sB = 0.f, ssB = 0.f;
    #pragma unroll
    for (int k = 0; k < 32; ++k) {
        float4 a = rowA[lane + 32 * k];
        float4 c = rowB[lane + 32 * k];
        sA  += (a.x + a.y) + (a.z + a.w);
        ssA += a.x * a.x + a.y * a.y + a.z * a.z + a.w * a.w;
        sB  += (c.x + c.y) + (c.z + c.w);
        ssB += c.x * c.x + c.y * c.y + c.z * c.z + c.w * c.w;
    }
    #pragma unroll
    for (int m = 16; m; m >>= 1) {
        sA  += __shfl_xor_sync(0xffffffffu, sA,  m);
        ssA += __shfl_xor_sync(0xffffffffu, ssA, m);
        sB  += __shfl_xor_sync(0xffffffffu, sB,  m);
        ssB += __shfl_xor_sync(0xffffffffu, ssB, m);
    }
    if (lane == 0) {
        float meanA = sA * (1.0f / DT);
        float meanB = sB * (1.0f / DT);
        e_scratch[b * NN + r0]     = (ssA - sA * meanA) * (1.0f / (DT - 1));
        e_scratch[b * NN + r0 + 1] = (ssB - sB * meanB) * (1.0f / (DT - 1));
    }
}

// ============================================================================
// K2: softmax (from e_scratch) + tf32 GEMM + exact fp32 residual.
// Grid 512 = (batch, t-half). 16 chunks of 128 t, double-buffered cp.async.
// Mainloop identical to R10's proven form: LDS fp32 -> cvt (ALU) -> mma.
// ============================================================================
__global__ void __launch_bounds__(THREADS, 2)
dga_gemm(const float* __restrict__ x,  const float* __restrict__ wq,
         const float* __restrict__ bq, const float* __restrict__ wk,
         const float* __restrict__ bk, float* __restrict__ out,
         float* __restrict__ attn)
{
    extern __shared__ float smf[];
    float* w_sm  = smf + SMF_W;
    float* e_sm  = smf + SMF_E;
    float* coef  = smf + SMF_CF;
    float* xbuf0 = smf + SMF_X0;
    float* xbuf1 = smf + SMF_X1;

    const int b    = blockIdx.x >> 1;
    const int half = blockIdx.x & 1;
    const int tid  = threadIdx.x;
    const int warp = tid >> 5;
    const int lane = tid & 31;
    const float* xb = x   + (size_t)b * NN * DT;
    float*       ob = out + (size_t)b * NN * DT;
    const int tbase = half * 2048;

    // ---- prologue: stage chunk 0 (fills under softmax) ----
    #pragma unroll
    for (int s = 0; s < 8; ++s) {
        int u = tid + 256 * s;
        int j = u >> 5, q = u & 31;
        cp_async16(&xbuf0[j * XSTR + q * 4], xb + (size_t)j * DT + tbase + q * 4);
    }
    asm volatile("cp.async.commit_group;");

    // ---- softmax weights ----
    if (tid < NN) e_sm[tid] = e_scratch[b * NN + tid];
    if (tid == 0) {
        float A = 0.f, B = 0.f, C = 0.f, Dc = 0.f;
        #pragma unroll
        for (int h = 0; h < 16; ++h) {
            float q = wq[h], qb = bq[h], k = wk[h], kb = bk[h];
            A += q * k; B += q * kb; C += qb * k; Dc += qb * kb;
        }
        coef[0] = A; coef[1] = B; coef[2] = C; coef[3] = Dc;
    }
    __syncthreads();
    {
        const int i  = tid >> 2;
        const int jg = tid & 3;
        const float ei = e_sm[i];
        const float m1 = 0.25f * (coef[0] * ei + coef[2]);   // SCALE = 0.25
        const float m0 = 0.25f * (coef[1] * ei + coef[3]);
        float sv[16];
        float mx = -3.4e38f;
        #pragma unroll
        for (int t = 0; t < 16; ++t) {
            int j = jg * 16 + t;
            float s = fmaf(m1, e_sm[j], m0);
            if (j == i) s = -1000000000.0f;
            sv[t] = s;
            mx = fmaxf(mx, s);
        }
        #pragma unroll
        for (int m = 1; m < 4; m <<= 1)
            mx = fmaxf(mx, __shfl_xor_sync(0xffffffffu, mx, m));
        float sum = 0.f;
        #pragma unroll
        for (int t = 0; t < 16; ++t) { sv[t] = __expf(sv[t] - mx); sum += sv[t]; }
        #pragma unroll
        for (int m = 1; m < 4; m <<= 1)
            sum += __shfl_xor_sync(0xffffffffu, sum, m);
        float inv = 1.0f / sum;

        float* arow = attn + (((size_t)b * NN) + i) * NN;
        #pragma unroll
        for (int t = 0; t < 16; ++t) {
            float w = sv[t] * inv;
            w_sm[i * WSTR + jg * 16 + t] = w;
            if (half == 0) arow[jg * 16 + t] = w;   // one half writes attn
        }
    }
    __syncthreads();

    // ---- A-fragments (W as tf32) in registers ----
    const int mw  = (warp & 3) * 16;
    const int nco = (warp >> 2) * 64;
    const int g   = lane >> 2;
    const int tg  = lane & 3;

    uint32_t A[8][4];
    #pragma unroll
    for (int ks = 0; ks < 8; ++ks) {
        A[ks][0] = f2tf32(w_sm[(mw + g)     * WSTR + ks * 8 + tg]);
        A[ks][1] = f2tf32(w_sm[(mw + g + 8) * WSTR + ks * 8 + tg]);
        A[ks][2] = f2tf32(w_sm[(mw + g)     * WSTR + ks * 8 + tg + 4]);
        A[ks][3] = f2tf32(w_sm[(mw + g + 8) * WSTR + ks * 8 + tg + 4]);
    }

    // ---- 16 chunks of 128 t, double-buffered (R10 mainloop verbatim) ----
    #pragma unroll 1
    for (int c = 0; c < 16; ++c) {
        const int t0 = tbase + c * 128;
        float* xc = (c & 1) ? xbuf1 : xbuf0;

        if (c + 1 < 16) {
            float* xn = (c & 1) ? xbuf0 : xbuf1;
            const float* src = xb + (t0 + 128);
            #pragma unroll
            for (int s = 0; s < 8; ++s) {
                int u = tid + 256 * s;
                int j = u >> 5, q = u & 31;
                cp_async16(&xn[j * XSTR + q * 4], src + (size_t)j * DT + q * 4);
            }
            asm volatile("cp.async.commit_group;");
            asm volatile("cp.async.wait_group 1;");
        } else {
            asm volatile("cp.async.wait_group 0;");
        }
        __syncthreads();

        float C[8][4];
        #pragma unroll
        for (int t = 0; t < 8; ++t)
            C[t][0] = C[t][1] = C[t][2] = C[t][3] = 0.f;

        #pragma unroll
        for (int ks = 0; ks < 8; ++ks) {
            const float* b0r = &xc[(ks * 8 + tg)     * XSTR + nco + g];
            const float* b1r = &xc[(ks * 8 + tg + 4) * XSTR + nco + g];
            #pragma unroll
            for (int t = 0; t < 8; ++t) {
                uint32_t b0 = f2tf32(b0r[t * 8]);     // single-phase LDS.32
                uint32_t b1 = f2tf32(b1r[t * 8]);
                mma_tf32(C[t][0], C[t][1], C[t][2], C[t][3],
                         A[ks][0], A[ks][1], A[ks][2], A[ks][3], b0, b1);
            }
        }

        // epilogue: exact fp32 residual from smem; plain stores
        #pragma unroll
        for (int t = 0; t < 8; ++t) {
            int lcol = nco + t * 8 + 2 * tg;
            float2 r0 = *(const float2*)&xc[(mw + g)     * XSTR + lcol];
            float2 r1 = *(const float2*)&xc[(mw + g + 8) * XSTR + lcol];
            *(float2*)(ob + (size_t)(mw + g)     * DT + t0 + lcol) =
                make_float2(C[t][0] + r0.x, C[t][1] + r0.y);
            *(float2*)(ob + (size_t)(mw + g + 8) * DT + t0 + lcol) =
                make_float2(C[t][2] + r1.x, C[t][3] + r1.y);
        }
        __syncthreads();   // compute(c) done before restaging this buffer
    }
}

extern "C" void kernel_launch(void* const* d_in, const int* in_sizes, int n_in,
                              void* d_out, int out_size) {
    const float* x  = (const float*)d_in[0];
    const float* wq = (const float*)d_in[1];
    const float* bq = (const float*)d_in[2];
    const float* wk = (const float*)d_in[3];
    const float* bk = (const float*)d_in[4];
    float* out  = (float*)d_out;
    float* attn = out + (size_t)NBATCH * NN * DT;   // out tensor first, then attn

    cudaFuncSetAttribute(dga_gemm, cudaFuncAttributeMaxDynamicSharedMemorySize,
                         SMEM_BYTES);

    dga_var <<<NBATCH * 4, THREADS>>>(x);
    dga_gemm<<<NBATCH * 2, THREADS, SMEM_BYTES>>>(x, wq, bq, wk, bk, out, attn);
}

// round 14
// speedup vs baseline: 1.3339x; 1.0432x over previous
#include <cuda_runtime.h>
#include <cstdint>

#define NBATCH 256
#define NN     64
#define DT     4096
#define THREADS 256

__device__ float e_scratch[NBATCH * NN];

#define CH   64                        // t per chunk
#define XSTR 72                        // floats; 72 % 32 == 8 -> conflict-free B LDS
#define WSTR 68
#define SMF_W  0                       // 64*68 = 4352 floats
#define SMF_X0 (SMF_W + NN * WSTR)     // 64*72 = 4608 floats
#define SMF_X1 (SMF_X0 + NN * XSTR)
#define SMF_E  (SMF_X1 + NN * XSTR)
#define SMF_CF (SMF_E + NN)
#define SMEM_FLOATS (SMF_CF + 8)
#define SMEM_BYTES  (SMEM_FLOATS * 4)  // ~54.6 KB -> 3 CTAs/SM

__device__ __forceinline__ uint32_t f2tf32(float f) {
    uint32_t r;
    asm("cvt.rna.tf32.f32 %0, %1;" : "=r"(r) : "f"(f));
    return r;
}
__device__ __forceinline__ void mma_tf32(float& c0, float& c1, float& c2, float& c3,
                                         uint32_t a0, uint32_t a1, uint32_t a2, uint32_t a3,
                                         uint32_t b0, uint32_t b1) {
    asm volatile(
        "mma.sync.aligned.m16n8k8.row.col.f32.tf32.tf32.f32 "
        "{%0,%1,%2,%3}, {%4,%5,%6,%7}, {%8,%9}, {%0,%1,%2,%3};"
        : "+f"(c0), "+f"(c1), "+f"(c2), "+f"(c3)
        : "r"(a0), "r"(a1), "r"(a2), "r"(a3), "r"(b0), "r"(b1));
}
__device__ __forceinline__ void cp_async16(void* smem_dst, const void* gsrc) {
    unsigned sa = (unsigned)__cvta_generic_to_shared(smem_dst);
    asm volatile("cp.async.cg.shared.global [%0], [%1], 16;" :: "r"(sa), "l"(gsrc));
}

// ============================================================================
// K1a: row variances (ddof=1). 1024 blocks, 2-row interleave (80.9% DRAM).
// ============================================================================
__global__ void __launch_bounds__(THREADS, 4)
dga_var(const float* __restrict__ x)
{
    const int b    = blockIdx.x >> 2;
    const int g    = blockIdx.x & 3;
    const int warp = threadIdx.x >> 5;
    const int lane = threadIdx.x & 31;
    const float* xb = x + (size_t)b * NN * DT;

    const int r0 = g * 16 + warp * 2;
    const float4* rowA = (const float4*)(xb + (size_t)r0 * DT);
    const float4* rowB = (const float4*)(xb + (size_t)(r0 + 1) * DT);
    float sA = 0.f, ssA = 0.f, sB = 0.f, ssB = 0.f;
    #pragma unroll
    for (int k = 0; k < 32; ++k) {
        float4 a = rowA[lane + 32 * k];
        float4 c = rowB[lane + 32 * k];
        sA  += (a.x + a.y) + (a.z + a.w);
        ssA += a.x * a.x + a.y * a.y + a.z * a.z + a.w * a.w;
        sB  += (c.x + c.y) + (c.z + c.w);
        ssB += c.x * c.x + c.y * c.y + c.z * c.z + c.w * c.w;
    }
    #pragma unroll
    for (int m = 16; m; m >>= 1) {
        sA  += __shfl_xor_sync(0xffffffffu, sA,  m);
        ssA += __shfl_xor_sync(0xffffffffu, ssA, m);
        sB  += __shfl_xor_sync(0xffffffffu, sB,  m);
        ssB += __shfl_xor_sync(0xffffffffu, ssB, m);
    }
    if (lane == 0) {
        float meanA = sA * (1.0f / DT);
        float meanB = sB * (1.0f / DT);
        e_scratch[b * NN + r0]     = (ssA - sA * meanA) * (1.0f / (DT - 1));
        e_scratch[b * NN + r0 + 1] = (ssB - sB * meanB) * (1.0f / (DT - 1));
    }
}

// ============================================================================
// K2: softmax (from e_scratch) + tf32 GEMM + exact fp32 residual.
// Grid 512 = (batch, t-half). 32 chunks of 64 t, double-buffered cp.async.
// 3 CTAs/SM. Mainloop: pure LDS.32 (raw fp32 bits -> tf32 truncation) + mma.
// ============================================================================
__global__ void __launch_bounds__(THREADS, 3)
dga_gemm(const float* __restrict__ x,  const float* __restrict__ wq,
         const float* __restrict__ bq, const float* __restrict__ wk,
         const float* __restrict__ bk, float* __restrict__ out,
         float* __restrict__ attn)
{
    extern __shared__ float smf[];
    float* w_sm  = smf + SMF_W;
    float* e_sm  = smf + SMF_E;
    float* coef  = smf + SMF_CF;
    float* xbuf0 = smf + SMF_X0;
    float* xbuf1 = smf + SMF_X1;

    const int b    = blockIdx.x >> 1;
    const int half = blockIdx.x & 1;
    const int tid  = threadIdx.x;
    const int warp = tid >> 5;
    const int lane = tid & 31;
    const float* xb = x   + (size_t)b * NN * DT;
    float*       ob = out + (size_t)b * NN * DT;
    const int tbase = half * 2048;

    // ---- prologue: stage chunk 0 (fills under softmax) ----
    #pragma unroll
    for (int s = 0; s < 4; ++s) {
        int u = tid + 256 * s;           // 1024 x 16B
        int j = u >> 4, q = u & 15;
        cp_async16(&xbuf0[j * XSTR + q * 4], xb + (size_t)j * DT + tbase + q * 4);
    }
    asm volatile("cp.async.commit_group;");

    // ---- softmax weights ----
    if (tid < NN) e_sm[tid] = e_scratch[b * NN + tid];
    if (tid == 0) {
        float A = 0.f, B = 0.f, C = 0.f, Dc = 0.f;
        #pragma unroll
        for (int h = 0; h < 16; ++h) {
            float q = wq[h], qb = bq[h], k = wk[h], kb = bk[h];
            A += q * k; B += q * kb; C += qb * k; Dc += qb * kb;
        }
        coef[0] = A; coef[1] = B; coef[2] = C; coef[3] = Dc;
    }
    __syncthreads();
    {
        const int i  = tid >> 2;
        const int jg = tid & 3;
        const float ei = e_sm[i];
        const float m1 = 0.25f * (coef[0] * ei + coef[2]);   // SCALE = 0.25
        const float m0 = 0.25f * (coef[1] * ei + coef[3]);
        float sv[16];
        float mx = -3.4e38f;
        #pragma unroll
        for (int t = 0; t < 16; ++t) {
            int j = jg * 16 + t;
            float s = fmaf(m1, e_sm[j], m0);
            if (j == i) s = -1000000000.0f;
            sv[t] = s;
            mx = fmaxf(mx, s);
        }
        #pragma unroll
        for (int m = 1; m < 4; m <<= 1)
            mx = fmaxf(mx, __shfl_xor_sync(0xffffffffu, mx, m));
        float sum = 0.f;
        #pragma unroll
        for (int t = 0; t < 16; ++t) { sv[t] = __expf(sv[t] - mx); sum += sv[t]; }
        #pragma unroll
        for (int m = 1; m < 4; m <<= 1)
            sum += __shfl_xor_sync(0xffffffffu, sum, m);
        float inv = 1.0f / sum;

        float* arow = attn + (((size_t)b * NN) + i) * NN;
        #pragma unroll
        for (int t = 0; t < 16; ++t) {
            float w = sv[t] * inv;
            w_sm[i * WSTR + jg * 16 + t] = w;
            if (half == 0) arow[jg * 16 + t] = w;   // one half writes attn
        }
    }
    __syncthreads();

    // ---- A-fragments (W as tf32, rounded) in registers ----
    const int mw  = (warp & 3) * 16;       // warp's 16 output rows
    const int nco = (warp >> 2) * 32;      // warp's 32-t slice within chunk
    const int g   = lane >> 2;
    const int tg  = lane & 3;

    uint32_t A[8][4];
    #pragma unroll
    for (int ks = 0; ks < 8; ++ks) {
        A[ks][0] = f2tf32(w_sm[(mw + g)     * WSTR + ks * 8 + tg]);
        A[ks][1] = f2tf32(w_sm[(mw + g + 8) * WSTR + ks * 8 + tg]);
        A[ks][2] = f2tf32(w_sm[(mw + g)     * WSTR + ks * 8 + tg + 4]);
        A[ks][3] = f2tf32(w_sm[(mw + g + 8) * WSTR + ks * 8 + tg + 4]);
    }

    // ---- 32 chunks of 64 t, double-buffered ----
    #pragma unroll 1
    for (int c = 0; c < 32; ++c) {
        const int t0 = tbase + c * CH;
        float* xc = (c & 1) ? xbuf1 : xbuf0;

        if (c + 1 < 32) {
            float* xn = (c & 1) ? xbuf0 : xbuf1;
            const float* src = xb + (t0 + CH);
            #pragma unroll
            for (int s = 0; s < 4; ++s) {
                int u = tid + 256 * s;
                int j = u >> 4, q = u & 15;
                cp_async16(&xn[j * XSTR + q * 4], src + (size_t)j * DT + q * 4);
            }
            asm volatile("cp.async.commit_group;");
            asm volatile("cp.async.wait_group 1;");
        } else {
            asm volatile("cp.async.wait_group 0;");
        }
        __syncthreads();

        // mainloop: raw fp32 bits as tf32 (HW truncates) — no cvt at all
        const uint32_t* xt = (const uint32_t*)xc;
        float C[4][4];
        #pragma unroll
        for (int t = 0; t < 4; ++t)
            C[t][0] = C[t][1] = C[t][2] = C[t][3] = 0.f;

        #pragma unroll
        for (int ks = 0; ks < 8; ++ks) {
            const uint32_t* b0r = &xt[(ks * 8 + tg)     * XSTR + nco + g];
            const uint32_t* b1r = &xt[(ks * 8 + tg + 4) * XSTR + nco + g];
            #pragma unroll
            for (int t = 0; t < 4; ++t) {
                uint32_t b0 = b0r[t * 8];         // single-phase LDS.32
                uint32_t b1 = b1r[t * 8];
                mma_tf32(C[t][0], C[t][1], C[t][2], C[t][3],
                         A[ks][0], A[ks][1], A[ks][2], A[ks][3], b0, b1);
            }
        }

        // epilogue: exact fp32 residual from smem; plain stores
        #pragma unroll
        for (int t = 0; t < 4; ++t) {
            int lcol = nco + t * 8 + 2 * tg;
            float2 r0 = *(const float2*)&xc[(mw + g)     * XSTR + lcol];
            float2 r1 = *(const float2*)&xc[(mw + g + 8) * XSTR + lcol];
            *(float2*)(ob + (size_t)(mw + g)     * DT + t0 + lcol) =
                make_float2(C[t][0] + r0.x, C[t][1] + r0.y);
            *(float2*)(ob + (size_t)(mw + g + 8) * DT + t0 + lcol) =
                make_float2(C[t][2] + r1.x, C[t][3] + r1.y);
        }
        __syncthreads();   // compute(c) done before restaging this buffer
    }
}

extern "C" void kernel_launch(void* const* d_in, const int* in_sizes, int n_in,
                              void* d_out, int out_size) {
    const float* x  = (const float*)d_in[0];
    const float* wq = (const float*)d_in[1];
    const float* bq = (const float*)d_in[2];
    const float* wk = (const float*)d_in[3];
    const float* bk = (const float*)d_in[4];
    float* out  = (float*)d_out;
    float* attn = out + (size_t)NBATCH * NN * DT;   // out tensor first, then attn

    cudaFuncSetAttribute(dga_gemm, cudaFuncAttributeMaxDynamicSharedMemorySize,
                         SMEM_BYTES);

    dga_var <<<NBATCH * 4, THREADS>>>(x);
    dga_gemm<<<NBATCH * 2, THREADS, SMEM_BYTES>>>(x, wq, bq, wk, bk, out, attn);
}

// round 15
// speedup vs baseline: 1.3599x; 1.0195x over previous
#include <cuda_runtime.h>
#include <cstdint>

#define NBATCH 256
#define NN     64
#define DT     4096
#define THREADS 256

__device__ float e_scratch[NBATCH * NN];

#define CH   64                        // t per chunk
#define XSTR 72                        // floats; 72 % 32 == 8 -> conflict-free B LDS
#define WSTR 68
#define SMF_W  0                       // 64*68 = 4352 floats
#define SMF_X  (SMF_W + NN * WSTR)     // 3 buffers of 64*72 = 4608 floats
#define XBUF   (NN * XSTR)
#define SMF_E  (SMF_X + 3 * XBUF)
#define SMF_CF (SMF_E + NN)
#define SMEM_FLOATS (SMF_CF + 8)
#define SMEM_BYTES  (SMEM_FLOATS * 4)  // 72992 B -> 3 CTAs/SM (3x73 = 219 <= 228 KB)

__device__ __forceinline__ uint32_t f2tf32(float f) {
    uint32_t r;
    asm("cvt.rna.tf32.f32 %0, %1;" : "=r"(r) : "f"(f));
    return r;
}
__device__ __forceinline__ void mma_tf32(float& c0, float& c1, float& c2, float& c3,
                                         uint32_t a0, uint32_t a1, uint32_t a2, uint32_t a3,
                                         uint32_t b0, uint32_t b1) {
    asm volatile(
        "mma.sync.aligned.m16n8k8.row.col.f32.tf32.tf32.f32 "
        "{%0,%1,%2,%3}, {%4,%5,%6,%7}, {%8,%9}, {%0,%1,%2,%3};"
        : "+f"(c0), "+f"(c1), "+f"(c2), "+f"(c3)
        : "r"(a0), "r"(a1), "r"(a2), "r"(a3), "r"(b0), "r"(b1));
}
__device__ __forceinline__ void cp_async16(void* smem_dst, const void* gsrc) {
    unsigned sa = (unsigned)__cvta_generic_to_shared(smem_dst);
    asm volatile("cp.async.cg.shared.global [%0], [%1], 16;" :: "r"(sa), "l"(gsrc));
}

// ============================================================================
// K1a: row variances (ddof=1). 1024 blocks, 2-row interleave (80.9% DRAM).
// Processes batches in ASCENDING order (K2 consumes them descending).
// ============================================================================
__global__ void __launch_bounds__(THREADS, 4)
dga_var(const float* __restrict__ x)
{
    const int b    = blockIdx.x >> 2;
    const int g    = blockIdx.x & 3;
    const int warp = threadIdx.x >> 5;
    const int lane = threadIdx.x & 31;
    const float* xb = x + (size_t)b * NN * DT;

    const int r0 = g * 16 + warp * 2;
    const float4* rowA = (const float4*)(xb + (size_t)r0 * DT);
    const float4* rowB = (const float4*)(xb + (size_t)(r0 + 1) * DT);
    float sA = 0.f, ssA = 0.f, sB = 0.f, ssB = 0.f;
    #pragma unroll
    for (int k = 0; k < 32; ++k) {
        float4 a = rowA[lane + 32 * k];
        float4 c = rowB[lane + 32 * k];
        sA  += (a.x + a.y) + (a.z + a.w);
        ssA += a.x * a.x + a.y * a.y + a.z * a.z + a.w * a.w;
        sB  += (c.x + c.y) + (c.z + c.w);
        ssB += c.x * c.x + c.y * c.y + c.z * c.z + c.w * c.w;
    }
    #pragma unroll
    for (int m = 16; m; m >>= 1) {
        sA  += __shfl_xor_sync(0xffffffffu, sA,  m);
        ssA += __shfl_xor_sync(0xffffffffu, ssA, m);
        sB  += __shfl_xor_sync(0xffffffffu, sB,  m);
        ssB += __shfl_xor_sync(0xffffffffu, ssB, m);
    }
    if (lane == 0) {
        float meanA = sA * (1.0f / DT);
        float meanB = sB * (1.0f / DT);
        e_scratch[b * NN + r0]     = (ssA - sA * meanA) * (1.0f / (DT - 1));
        e_scratch[b * NN + r0 + 1] = (ssB - sB * meanB) * (1.0f / (DT - 1));
    }
}

// ============================================================================
// K2: softmax (from e_scratch) + tf32 GEMM + exact fp32 residual.
// Grid 512 = (batch DESCENDING, t-half): first K2 batches are the last K1a
// read -> L2-hot. 32 chunks of 64 t in a 3-buffer ring: ONE barrier/chunk.
// 3 CTAs/SM. Mainloop: pure LDS.32 (raw fp32 bits as tf32) + mma.
// ============================================================================
__global__ void __launch_bounds__(THREADS, 3)
dga_gemm(const float* __restrict__ x,  const float* __restrict__ wq,
         const float* __restrict__ bq, const float* __restrict__ wk,
         const float* __restrict__ bk, float* __restrict__ out,
         float* __restrict__ attn)
{
    extern __shared__ float smf[];
    float* w_sm = smf + SMF_W;
    float* e_sm = smf + SMF_E;
    float* coef = smf + SMF_CF;

    const int b    = (NBATCH - 1) - (blockIdx.x >> 1);   // descending batches
    const int half = blockIdx.x & 1;
    const int tid  = threadIdx.x;
    const int warp = tid >> 5;
    const int lane = tid & 31;
    const float* xb = x   + (size_t)b * NN * DT;
    float*       ob = out + (size_t)b * NN * DT;
    const int tbase = half * 2048;

    // ---- prologue: stage chunk 0 into buffer 0 (fills under softmax) ----
    {
        float* x0 = smf + SMF_X;
        #pragma unroll
        for (int s = 0; s < 4; ++s) {
            int u = tid + 256 * s;           // 1024 x 16B
            int j = u >> 4, q = u & 15;
            cp_async16(&x0[j * XSTR + q * 4], xb + (size_t)j * DT + tbase + q * 4);
        }
        asm volatile("cp.async.commit_group;");
    }

    // ---- softmax weights ----
    if (tid < NN) e_sm[tid] = e_scratch[b * NN + tid];
    if (tid == 0) {
        float A = 0.f, B = 0.f, C = 0.f, Dc = 0.f;
        #pragma unroll
        for (int h = 0; h < 16; ++h) {
            float q = wq[h], qb = bq[h], k = wk[h], kb = bk[h];
            A += q * k; B += q * kb; C += qb * k; Dc += qb * kb;
        }
        coef[0] = A; coef[1] = B; coef[2] = C; coef[3] = Dc;
    }
    __syncthreads();
    {
        const int i  = tid >> 2;
        const int jg = tid & 3;
        const float ei = e_sm[i];
        const float m1 = 0.25f * (coef[0] * ei + coef[2]);   // SCALE = 0.25
        const float m0 = 0.25f * (coef[1] * ei + coef[3]);
        float sv[16];
        float mx = -3.4e38f;
        #pragma unroll
        for (int t = 0; t < 16; ++t) {
            int j = jg * 16 + t;
            float s = fmaf(m1, e_sm[j], m0);
            if (j == i) s = -1000000000.0f;
            sv[t] = s;
            mx = fmaxf(mx, s);
        }
        #pragma unroll
        for (int m = 1; m < 4; m <<= 1)
            mx = fmaxf(mx, __shfl_xor_sync(0xffffffffu, mx, m));
        float sum = 0.f;
        #pragma unroll
        for (int t = 0; t < 16; ++t) { sv[t] = __expf(sv[t] - mx); sum += sv[t]; }
        #pragma unroll
        for (int m = 1; m < 4; m <<= 1)
            sum += __shfl_xor_sync(0xffffffffu, sum, m);
        float inv = 1.0f / sum;

        float* arow = attn + (((size_t)b * NN) + i) * NN;
        #pragma unroll
        for (int t = 0; t < 16; ++t) {
            float w = sv[t] * inv;
            w_sm[i * WSTR + jg * 16 + t] = w;
            if (half == 0) arow[jg * 16 + t] = w;   // one half writes attn
        }
    }
    __syncthreads();

    // ---- A-fragments (W as tf32, rounded) in registers ----
    const int mw  = (warp & 3) * 16;       // warp's 16 output rows
    const int nco = (warp >> 2) * 32;      // warp's 32-t slice within chunk
    const int g   = lane >> 2;
    const int tg  = lane & 3;

    uint32_t A[8][4];
    #pragma unroll
    for (int ks = 0; ks < 8; ++ks) {
        A[ks][0] = f2tf32(w_sm[(mw + g)     * WSTR + ks * 8 + tg]);
        A[ks][1] = f2tf32(w_sm[(mw + g + 8) * WSTR + ks * 8 + tg]);
        A[ks][2] = f2tf32(w_sm[(mw + g)     * WSTR + ks * 8 + tg + 4]);
        A[ks][3] = f2tf32(w_sm[(mw + g + 8) * WSTR + ks * 8 + tg + 4]);
    }

    // ---- 32 chunks of 64 t; 3-buffer ring; one barrier per chunk ----
    // stage(c+1) writes buf (c+1)%3, last read at compute(c-2) which is
    // ordered before sync(c-1) for all warps -> no trailing barrier needed.
    #pragma unroll 1
    for (int c = 0; c < 32; ++c) {
        const int t0 = tbase + c * CH;
        float* xc = smf + SMF_X + (c % 3) * XBUF;

        if (c + 1 < 32) {
            float* xn = smf + SMF_X + ((c + 1) % 3) * XBUF;
            const float* src = xb + (t0 + CH);
            #pragma unroll
            for (int s = 0; s < 4; ++s) {
                int u = tid + 256 * s;
                int j = u >> 4, q = u & 15;
                cp_async16(&xn[j * XSTR + q * 4], src + (size_t)j * DT + q * 4);
            }
            asm volatile("cp.async.commit_group;");
            asm volatile("cp.async.wait_group 1;");   // chunk c landed
        } else {
            asm volatile("cp.async.wait_group 0;");
        }
        __syncthreads();                              // sole barrier per chunk

        // mainloop: raw fp32 bits as tf32 (HW truncates) — no cvt at all
        const uint32_t* xt = (const uint32_t*)xc;
        float C[4][4];
        #pragma unroll
        for (int t = 0; t < 4; ++t)
            C[t][0] = C[t][1] = C[t][2] = C[t][3] = 0.f;

        #pragma unroll
        for (int ks = 0; ks < 8; ++ks) {
            const uint32_t* b0r = &xt[(ks * 8 + tg)     * XSTR + nco + g];
            const uint32_t* b1r = &xt[(ks * 8 + tg + 4) * XSTR + nco + g];
            #pragma unroll
            for (int t = 0; t < 4; ++t) {
                uint32_t b0 = b0r[t * 8];             // single-phase LDS.32
                uint32_t b1 = b1r[t * 8];
                mma_tf32(C[t][0], C[t][1], C[t][2], C[t][3],
                         A[ks][0], A[ks][1], A[ks][2], A[ks][3], b0, b1);
            }
        }

        // epilogue: exact fp32 residual from smem; plain stores
        #pragma unroll
        for (int t = 0; t < 4; ++t) {
            int lcol = nco + t * 8 + 2 * tg;
            float2 r0 = *(const float2*)&xc[(mw + g)     * XSTR + lcol];
            float2 r1 = *(const float2*)&xc[(mw + g + 8) * XSTR + lcol];
            *(float2*)(ob + (size_t)(mw + g)     * DT + t0 + lcol) =
                make_float2(C[t][0] + r0.x, C[t][1] + r0.y);
            *(float2*)(ob + (size_t)(mw + g + 8) * DT + t0 + lcol) =
                make_float2(C[t][2] + r1.x, C[t][3] + r1.y);
        }
    }
}

extern "C" void kernel_launch(void* const* d_in, const int* in_sizes, int n_in,
                              void* d_out, int out_size) {
    const float* x  = (const float*)d_in[0];
    const float* wq = (const float*)d_in[1];
    const float* bq = (const float*)d_in[2];
    const float* wk = (const float*)d_in[3];
    const float* bk = (const float*)d_in[4];
    float* out  = (float*)d_out;
    float* attn = out + (size_t)NBATCH * NN * DT;   // out tensor first, then attn

    cudaFuncSetAttribute(dga_gemm, cudaFuncAttributeMaxDynamicSharedMemorySize,
                         SMEM_BYTES);

    dga_var <<<NBATCH * 4, THREADS>>>(x);
    dga_gemm<<<NBATCH * 2, THREADS, SMEM_BYTES>>>(x, wq, bq, wk, bk, out, attn);
}

// round 16
// speedup vs baseline: 1.3616x; 1.0012x over previous
#include <cuda_runtime.h>
#include <cstdint>

#define NBATCH 256
#define NN     64
#define DT     4096
#define THREADS 256

__device__ float    e_scratch[NBATCH * NN];
#define WSTR 68
__device__ uint32_t w_scratch[NBATCH * NN * WSTR];   // tf32 bits of softmax W

#define CH   64                        // t per chunk
#define XSTR 72                        // floats; 72 % 32 == 8 -> conflict-free B LDS
#define XBUF (NN * XSTR)               // 4608 floats per buffer
#define SMEM_BYTES (3 * XBUF * 4)      // 55296 B -> 3 CTAs/SM

__device__ __forceinline__ uint32_t f2tf32(float f) {
    uint32_t r;
    asm("cvt.rna.tf32.f32 %0, %1;" : "=r"(r) : "f"(f));
    return r;
}
__device__ __forceinline__ void mma_tf32(float& c0, float& c1, float& c2, float& c3,
                                         uint32_t a0, uint32_t a1, uint32_t a2, uint32_t a3,
                                         uint32_t b0, uint32_t b1) {
    asm volatile(
        "mma.sync.aligned.m16n8k8.row.col.f32.tf32.tf32.f32 "
        "{%0,%1,%2,%3}, {%4,%5,%6,%7}, {%8,%9}, {%0,%1,%2,%3};"
        : "+f"(c0), "+f"(c1), "+f"(c2), "+f"(c3)
        : "r"(a0), "r"(a1), "r"(a2), "r"(a3), "r"(b0), "r"(b1));
}
__device__ __forceinline__ void cp_async16(void* smem_dst, const void* gsrc) {
    unsigned sa = (unsigned)__cvta_generic_to_shared(smem_dst);
    asm volatile("cp.async.cg.shared.global [%0], [%1], 16;" :: "r"(sa), "l"(gsrc));
}

// ============================================================================
// K1a: row variances (ddof=1). 1024 blocks, 2-row interleave (80.9% DRAM).
// ============================================================================
__global__ void __launch_bounds__(THREADS, 4)
dga_var(const float* __restrict__ x)
{
    const int b    = blockIdx.x >> 2;
    const int g    = blockIdx.x & 3;
    const int warp = threadIdx.x >> 5;
    const int lane = threadIdx.x & 31;
    const float* xb = x + (size_t)b * NN * DT;

    const int r0 = g * 16 + warp * 2;
    const float4* rowA = (const float4*)(xb + (size_t)r0 * DT);
    const float4* rowB = (const float4*)(xb + (size_t)(r0 + 1) * DT);
    float sA = 0.f, ssA = 0.f, sB = 0.f, ssB = 0.f;
    #pragma unroll
    for (int k = 0; k < 32; ++k) {
        float4 a = rowA[lane + 32 * k];
        float4 c = rowB[lane + 32 * k];
        sA  += (a.x + a.y) + (a.z + a.w);
        ssA += a.x * a.x + a.y * a.y + a.z * a.z + a.w * a.w;
        sB  += (c.x + c.y) + (c.z + c.w);
        ssB += c.x * c.x + c.y * c.y + c.z * c.z + c.w * c.w;
    }
    #pragma unroll
    for (int m = 16; m; m >>= 1) {
        sA  += __shfl_xor_sync(0xffffffffu, sA,  m);
        ssA += __shfl_xor_sync(0xffffffffu, ssA, m);
        sB  += __shfl_xor_sync(0xffffffffu, sB,  m);
        ssB += __shfl_xor_sync(0xffffffffu, ssB, m);
    }
    if (lane == 0) {
        float meanA = sA * (1.0f / DT);
        float meanB = sB * (1.0f / DT);
        e_scratch[b * NN + r0]     = (ssA - sA * meanA) * (1.0f / (DT - 1));
        e_scratch[b * NN + r0 + 1] = (ssB - sB * meanB) * (1.0f / (DT - 1));
    }
}

// ============================================================================
// K1b: coefs -> masked softmax -> attn (fp32) + w_scratch (tf32 bits).
// 256 blocks. Removes all softmax work from K2.
// ============================================================================
__global__ void __launch_bounds__(THREADS)
dga_weights(const float* __restrict__ wq, const float* __restrict__ bq,
            const float* __restrict__ wk, const float* __restrict__ bk,
            float* __restrict__ attn)
{
    __shared__ float e_sm[NN];
    __shared__ float coef[4];

    const int b   = blockIdx.x;
    const int tid = threadIdx.x;

    if (tid < NN) e_sm[tid] = e_scratch[b * NN + tid];
    if (tid == 0) {
        float A = 0.f, B = 0.f, C = 0.f, Dc = 0.f;
        #pragma unroll
        for (int h = 0; h < 16; ++h) {
            float q = wq[h], qb = bq[h], k = wk[h], kb = bk[h];
            A += q * k; B += q * kb; C += qb * k; Dc += qb * kb;
        }
        coef[0] = A; coef[1] = B; coef[2] = C; coef[3] = Dc;
    }
    __syncthreads();

    const int i  = tid >> 2;
    const int jg = tid & 3;
    const float ei = e_sm[i];
    const float m1 = 0.25f * (coef[0] * ei + coef[2]);   // SCALE = 0.25
    const float m0 = 0.25f * (coef[1] * ei + coef[3]);
    float sv[16];
    float mx = -3.4e38f;
    #pragma unroll
    for (int t = 0; t < 16; ++t) {
        int j = jg * 16 + t;
        float s = fmaf(m1, e_sm[j], m0);
        if (j == i) s = -1000000000.0f;
        sv[t] = s;
        mx = fmaxf(mx, s);
    }
    #pragma unroll
    for (int m = 1; m < 4; m <<= 1)
        mx = fmaxf(mx, __shfl_xor_sync(0xffffffffu, mx, m));
    float sum = 0.f;
    #pragma unroll
    for (int t = 0; t < 16; ++t) { sv[t] = __expf(sv[t] - mx); sum += sv[t]; }
    #pragma unroll
    for (int m = 1; m < 4; m <<= 1)
        sum += __shfl_xor_sync(0xffffffffu, sum, m);
    float inv = 1.0f / sum;

    float*    arow = attn + (((size_t)b * NN) + i) * NN;
    uint32_t* wrow = w_scratch + ((size_t)b * NN + i) * WSTR;
    #pragma unroll
    for (int t = 0; t < 16; ++t) {
        float w = sv[t] * inv;
        arow[jg * 16 + t] = w;
        wrow[jg * 16 + t] = f2tf32(w);
    }
}

// ============================================================================
// K2: pure tf32 GEMM + exact fp32 residual. Grid 2048 = (batch desc, eighth).
// 8 chunks of 64 t; 3-buffer ring, one barrier/chunk; A-frags from w_scratch
// (L2-hot LDG, pre-converted). 3 CTAs/SM, 4.6 waves -> small tail.
// ============================================================================
__global__ void __launch_bounds__(THREADS, 3)
dga_gemm(const float* __restrict__ x, float* __restrict__ out)
{
    extern __shared__ float smf[];

    const int b    = (NBATCH - 1) - (blockIdx.x >> 3);   // descending batches
    const int sl   = blockIdx.x & 7;                     // t-eighth
    const int tid  = threadIdx.x;
    const int warp = tid >> 5;
    const int lane = tid & 31;
    const float* xb = x   + (size_t)b * NN * DT;
    float*       ob = out + (size_t)b * NN * DT;
    const int tbase = sl * 512;

    // ---- prologue: stage chunk 0 into buffer 0 ----
    {
        float* x0 = smf;
        #pragma unroll
        for (int s = 0; s < 4; ++s) {
            int u = tid + 256 * s;           // 1024 x 16B
            int j = u >> 4, q = u & 15;
            cp_async16(&x0[j * XSTR + q * 4], xb + (size_t)j * DT + tbase + q * 4);
        }
        asm volatile("cp.async.commit_group;");
    }

    // ---- A-fragments straight from w_scratch (tf32 bits, L2-hot) ----
    const int mw  = (warp & 3) * 16;       // warp's 16 output rows
    const int nco = (warp >> 2) * 32;      // warp's 32-t slice within chunk
    const int g   = lane >> 2;
    const int tg  = lane & 3;

    const uint32_t* wsb = w_scratch + (size_t)b * NN * WSTR;
    uint32_t A[8][4];
    #pragma unroll
    for (int ks = 0; ks < 8; ++ks) {
        A[ks][0] = wsb[(mw + g)     * WSTR + ks * 8 + tg];
        A[ks][1] = wsb[(mw + g + 8) * WSTR + ks * 8 + tg];
        A[ks][2] = wsb[(mw + g)     * WSTR + ks * 8 + tg + 4];
        A[ks][3] = wsb[(mw + g + 8) * WSTR + ks * 8 + tg + 4];
    }

    // ---- 8 chunks of 64 t; 3-buffer ring; one barrier per chunk ----
    #pragma unroll 1
    for (int c = 0; c < 8; ++c) {
        const int t0 = tbase + c * CH;
        float* xc = smf + (c % 3) * XBUF;

        if (c + 1 < 8) {
            float* xn = smf + ((c + 1) % 3) * XBUF;
            const float* src = xb + (t0 + CH);
            #pragma unroll
            for (int s = 0; s < 4; ++s) {
                int u = tid + 256 * s;
                int j = u >> 4, q = u & 15;
                cp_async16(&xn[j * XSTR + q * 4], src + (size_t)j * DT + q * 4);
            }
            asm volatile("cp.async.commit_group;");
            asm volatile("cp.async.wait_group 1;");   // chunk c landed
        } else {
            asm volatile("cp.async.wait_group 0;");
        }
        __syncthreads();                              // sole barrier per chunk

        // mainloop: raw fp32 bits as tf32 (HW truncates) — no cvt
        const uint32_t* xt = (const uint32_t*)xc;
        float C[4][4];
        #pragma unroll
        for (int t = 0; t < 4; ++t)
            C[t][0] = C[t][1] = C[t][2] = C[t][3] = 0.f;

        #pragma unroll
        for (int ks = 0; ks < 8; ++ks) {
            const uint32_t* b0r = &xt[(ks * 8 + tg)     * XSTR + nco + g];
            const uint32_t* b1r = &xt[(ks * 8 + tg + 4) * XSTR + nco + g];
            #pragma unroll
            for (int t = 0; t < 4; ++t) {
                uint32_t b0 = b0r[t * 8];             // single-phase LDS.32
                uint32_t b1 = b1r[t * 8];
                mma_tf32(C[t][0], C[t][1], C[t][2], C[t][3],
                         A[ks][0], A[ks][1], A[ks][2], A[ks][3], b0, b1);
            }
        }

        // epilogue: exact fp32 residual from smem; plain stores
        #pragma unroll
        for (int t = 0; t < 4; ++t) {
            int lcol = nco + t * 8 + 2 * tg;
            float2 r0 = *(const float2*)&xc[(mw + g)     * XSTR + lcol];
            float2 r1 = *(const float2*)&xc[(mw + g + 8) * XSTR + lcol];
            *(float2*)(ob + (size_t)(mw + g)     * DT + t0 + lcol) =
                make_float2(C[t][0] + r0.x, C[t][1] + r0.y);
            *(float2*)(ob + (size_t)(mw + g + 8) * DT + t0 + lcol) =
                make_float2(C[t][2] + r1.x, C[t][3] + r1.y);
        }
    }
}

extern "C" void kernel_launch(void* const* d_in, const int* in_sizes, int n_in,
                              void* d_out, int out_size) {
    const float* x  = (const float*)d_in[0];
    const float* wq = (const float*)d_in[1];
    const float* bq = (const float*)d_in[2];
    const float* wk = (const float*)d_in[3];
    const float* bk = (const float*)d_in[4];
    float* out  = (float*)d_out;
    float* attn = out + (size_t)NBATCH * NN * DT;   // out tensor first, then attn

    cudaFuncSetAttribute(dga_gemm, cudaFuncAttributeMaxDynamicSharedMemorySize,
                         SMEM_BYTES);

    dga_var    <<<NBATCH * 4, THREADS>>>(x);
    dga_weights<<<NBATCH,     THREADS>>>(wq, bq, wk, bk, attn);
    dga_gemm   <<<NBATCH * 8, THREADS, SMEM_BYTES>>>(x, out);
}